// round 9
// baseline (speedup 1.0000x reference)
#include <cuda_runtime.h>
#include <math.h>

#define F_IN   512
#define HID    16
#define CLS    40
#define N_MAX  100000
#define E_MAX  3400000
#define SCAN_B 1024
#define NBLK   ((N_MAX + SCAN_B - 1) / SCAN_B)   // 98

// ---------------- scratch (static device globals; no allocation) ------------
__device__ float  g_dis[N_MAX];                 // dis = rsqrt(deg)
__device__ int    g_cnt[N_MAX];                 // in-degree counts
__device__ int    g_off[N_MAX + 1];             // CSR offsets (by col)
__device__ int    g_cursor[N_MAX];              // fill cursors
__device__ int    g_bsum[NBLK];                 // per-block totals
__device__ int    g_boff[NBLK];                 // per-block exclusive offsets
__device__ unsigned long long g_csr[E_MAX];     // packed (w_bits<<32 | row)
__device__ float4 g_h1[N_MAX * 4];              // h1, scaled in place to dis*h1
__device__ float4 g_h2[N_MAX * 4];              // hd2 = dis*relu(layer1)

// ---------------- f32x2 packed math helpers (sm_10x FFMA2) ------------------
__device__ __forceinline__ unsigned long long pack2(float lo, float hi) {
    unsigned long long d;
    asm("mov.b64 %0, {%1,%2};" : "=l"(d) : "f"(lo), "f"(hi));
    return d;
}
__device__ __forceinline__ void unpack2(unsigned long long v, float& lo, float& hi) {
    asm("mov.b64 {%0,%1}, %2;" : "=f"(lo), "=f"(hi) : "l"(v));
}
__device__ __forceinline__ unsigned long long fma2(unsigned long long a,
                                                   unsigned long long b,
                                                   unsigned long long c) {
    unsigned long long d;
    asm("fma.rn.f32x2 %0, %1, %2, %3;" : "=l"(d) : "l"(a), "l"(b), "l"(c));
    return d;
}

// ---------------- init: cnt=0 ----------------------------------------------
__global__ void init_kernel(int N) {
    int i = blockIdx.x * blockDim.x + threadIdx.x;
    if (i < N) g_cnt[i] = 0;
}

// cnt[col] += 1
__global__ void cnt_kernel(const int* __restrict__ col, int E) {
    int e = blockIdx.x * blockDim.x + threadIdx.x;
    if (e < E) atomicAdd(&g_cnt[col[e]], 1);
}

// ---------------- 3-phase multi-block exclusive scan ------------------------
__global__ __launch_bounds__(SCAN_B) void scan1_kernel(int N) {
    __shared__ int s[SCAN_B];
    int t = threadIdx.x;
    int i = blockIdx.x * SCAN_B + t;
    int v = (i < N) ? g_cnt[i] : 0;
    s[t] = v;
    __syncthreads();
    #pragma unroll
    for (int d = 1; d < SCAN_B; d <<= 1) {
        int u = (t >= d) ? s[t - d] : 0;
        __syncthreads();
        s[t] += u;
        __syncthreads();
    }
    if (i < N) g_off[i] = s[t] - v;                 // exclusive
    if (t == SCAN_B - 1) g_bsum[blockIdx.x] = s[t]; // block total
}

__global__ __launch_bounds__(128) void scan2_kernel(int N) {
    __shared__ int s[128];
    int t = threadIdx.x;
    int v = (t < NBLK) ? g_bsum[t] : 0;
    s[t] = v;
    __syncthreads();
    #pragma unroll
    for (int d = 1; d < 128; d <<= 1) {
        int u = (t >= d) ? s[t - d] : 0;
        __syncthreads();
        s[t] += u;
        __syncthreads();
    }
    if (t < NBLK) g_boff[t] = s[t] - v;
    if (t == 127) g_off[N] = s[t];                  // grand total (= E)
}

__global__ void scan3_kernel(int N) {
    int i = blockIdx.x * blockDim.x + threadIdx.x;
    if (i < N) {
        int o = g_off[i] + g_boff[i / SCAN_B];
        g_off[i] = o;
        g_cursor[i] = o;
    }
}

// fill CSR: append (w, row) to col c.  No dis dependency, no norm math.
__global__ void fill_kernel(const int* __restrict__ ei, const float* __restrict__ w, int E) {
    int e = blockIdx.x * blockDim.x + threadIdx.x;
    if (e >= E) return;
    int r = ei[e];
    int c = ei[E + e];
    int pos = atomicAdd(&g_cursor[c], 1);
    g_csr[pos] = ((unsigned long long)__float_as_uint(w[e]) << 32) | (unsigned int)r;
}

// ---------------- dense GEMM: h1 = x @ W1 (f32x2 packed FFMA) ---------------
#define GT    64      // threads per block
#define GR    4       // rows per thread (2 packed pairs)
#define GROWS (GT*GR) // 256 rows per block
#define KC    16      // k-chunk

__global__ __launch_bounds__(GT) void gemm1_kernel(const float* __restrict__ x,
                                                   const float* __restrict__ W1,
                                                   int N) {
    __shared__ float xs[GROWS][KC + 1];            // +1 pad: bank-conflict-free
    __shared__ unsigned long long ws2[KC][HID];    // W duplicated (w,w)
    int r0 = blockIdx.x * GROWS;

    unsigned long long acc2[2][HID];
    #pragma unroll
    for (int p = 0; p < 2; p++)
        #pragma unroll
        for (int j = 0; j < HID; j++) acc2[p][j] = 0ULL;

    for (int kc = 0; kc < F_IN; kc += KC) {
        __syncthreads();
        for (int i = threadIdx.x; i < KC * HID; i += GT) {
            float wv = W1[(kc + i / HID) * HID + (i % HID)];
            ws2[i / HID][i % HID] = pack2(wv, wv);
        }
        for (int idx = threadIdx.x; idx < GROWS * (KC / 4); idx += GT) {
            int rl  = idx / (KC / 4);
            int c4  = idx % (KC / 4);
            int row = r0 + rl;
            float4 v = make_float4(0.f, 0.f, 0.f, 0.f);
            if (row < N)
                v = *(const float4*)(x + (size_t)row * F_IN + kc + c4 * 4);
            xs[rl][c4 * 4 + 0] = v.x;
            xs[rl][c4 * 4 + 1] = v.y;
            xs[rl][c4 * 4 + 2] = v.z;
            xs[rl][c4 * 4 + 3] = v.w;
        }
        __syncthreads();

        #pragma unroll 4
        for (int kk = 0; kk < KC; kk++) {
            unsigned long long wv[HID];
            #pragma unroll
            for (int j = 0; j < HID; j++) wv[j] = ws2[kk][j];
            #pragma unroll
            for (int p = 0; p < 2; p++) {
                float xa = xs[threadIdx.x + (2 * p + 0) * GT][kk];
                float xb = xs[threadIdx.x + (2 * p + 1) * GT][kk];
                unsigned long long xp = pack2(xa, xb);
                #pragma unroll
                for (int j = 0; j < HID; j++)
                    acc2[p][j] = fma2(xp, wv[j], acc2[p][j]);
            }
        }
    }

    #pragma unroll
    for (int p = 0; p < 2; p++) {
        float va[HID], vb[HID];
        #pragma unroll
        for (int j = 0; j < HID; j++) unpack2(acc2[p][j], va[j], vb[j]);
        int rowA = r0 + threadIdx.x + (2 * p + 0) * GT;
        int rowB = r0 + threadIdx.x + (2 * p + 1) * GT;
        if (rowA < N) {
            #pragma unroll
            for (int q = 0; q < 4; q++)
                g_h1[rowA * 4 + q] = make_float4(va[4*q], va[4*q+1], va[4*q+2], va[4*q+3]);
        }
        if (rowB < N) {
            #pragma unroll
            for (int q = 0; q < 4; q++)
                g_h1[rowB * 4 + q] = make_float4(vb[4*q], vb[4*q+1], vb[4*q+2], vb[4*q+3]);
        }
    }
}

// ---------------- deg from CSR; dis = rsqrt; scale h1 *= dis (warp/node) ----
__global__ __launch_bounds__(256) void degdis_kernel(int N) {
    int node = (blockIdx.x * blockDim.x + threadIdx.x) >> 5;
    int lane = threadIdx.x & 31;
    if (node >= N) return;
    int start = g_off[node];
    int end   = g_off[node + 1];
    float s = 0.f;
    for (int e = start + lane; e < end; e += 32)
        s += __uint_as_float((unsigned int)(g_csr[e] >> 32));
    #pragma unroll
    for (int m = 1; m < 32; m <<= 1)
        s += __shfl_xor_sync(0xffffffffu, s, m);
    float dis = rsqrtf(s + 1.0f);        // +1: self-loop weight; deg >= 1 > 0
    if (lane == 0) g_dis[node] = dis;
    if (lane < 4) {                       // h1 *= dis  (hd = dis*h)
        float4 h = g_h1[node * 4 + lane];
        g_h1[node * 4 + lane] = make_float4(dis * h.x, dis * h.y, dis * h.z, dis * h.w);
    }
}

// ---------------- gather layer 1: hd2 = dis*relu(dis*(Σ w·hd[r] + hd[c])+b1)-
__global__ __launch_bounds__(256) void gather1_kernel(const float* __restrict__ bias, int N) {
    int node = (blockIdx.x * blockDim.x + threadIdx.x) >> 5;
    int lane = threadIdx.x & 31;
    if (node >= N) return;

    int start = g_off[node];
    int end   = g_off[node + 1];
    int sub = lane >> 2;     // 0..7 : edge slot
    int q   = lane & 3;      // 0..3 : float4 quad

    float4 acc = make_float4(0.f, 0.f, 0.f, 0.f);
    for (int e = start + sub; e < end; e += 8) {
        unsigned long long en = g_csr[e];
        int   r = (int)(unsigned int)(en & 0xffffffffULL);
        float w = __uint_as_float((unsigned int)(en >> 32));
        float4 s = g_h1[r * 4 + q];
        acc.x = fmaf(w, s.x, acc.x);
        acc.y = fmaf(w, s.y, acc.y);
        acc.z = fmaf(w, s.z, acc.z);
        acc.w = fmaf(w, s.w, acc.w);
    }
    #pragma unroll
    for (int m = 4; m < 32; m <<= 1) {
        acc.x += __shfl_xor_sync(0xffffffffu, acc.x, m);
        acc.y += __shfl_xor_sync(0xffffffffu, acc.y, m);
        acc.z += __shfl_xor_sync(0xffffffffu, acc.z, m);
        acc.w += __shfl_xor_sync(0xffffffffu, acc.w, m);
    }
    if (lane < 4) {
        float dis = g_dis[node];
        float4 h = g_h1[node * 4 + lane];      // hd[node]: self-loop term
        float4 b = ((const float4*)bias)[lane];
        acc.x = dis * fmaxf(fmaf(dis, acc.x + h.x, b.x), 0.f);
        acc.y = dis * fmaxf(fmaf(dis, acc.y + h.y, b.y), 0.f);
        acc.z = dis * fmaxf(fmaf(dis, acc.z + h.z, b.z), 0.f);
        acc.w = dis * fmaxf(fmaf(dis, acc.w + h.w, b.w), 0.f);
        g_h2[node * 4 + lane] = acc;
    }
}

// ---------------- fused gather layer 2 + W2 GEMM + log_softmax --------------
__global__ __launch_bounds__(256) void gatherfinal_kernel(const float* __restrict__ W2,
                                                          const float* __restrict__ b2,
                                                          float* __restrict__ out,
                                                          int N) {
    __shared__ float w2s[HID][CLS];
    __shared__ float b2s[CLS];
    for (int i = threadIdx.x; i < HID * CLS; i += blockDim.x)
        w2s[i / CLS][i % CLS] = W2[i];
    if (threadIdx.x < CLS) b2s[threadIdx.x] = b2[threadIdx.x];
    __syncthreads();

    int node = (blockIdx.x * blockDim.x + threadIdx.x) >> 5;
    int lane = threadIdx.x & 31;
    if (node >= N) return;

    int start = g_off[node];
    int end   = g_off[node + 1];
    int sub = lane >> 2;
    int q   = lane & 3;

    float4 acc = make_float4(0.f, 0.f, 0.f, 0.f);
    for (int e = start + sub; e < end; e += 8) {
        unsigned long long en = g_csr[e];
        int   r = (int)(unsigned int)(en & 0xffffffffULL);
        float w = __uint_as_float((unsigned int)(en >> 32));
        float4 s = g_h2[r * 4 + q];
        acc.x = fmaf(w, s.x, acc.x);
        acc.y = fmaf(w, s.y, acc.y);
        acc.z = fmaf(w, s.z, acc.z);
        acc.w = fmaf(w, s.w, acc.w);
    }
    #pragma unroll
    for (int m = 4; m < 32; m <<= 1) {
        acc.x += __shfl_xor_sync(0xffffffffu, acc.x, m);
        acc.y += __shfl_xor_sync(0xffffffffu, acc.y, m);
        acc.z += __shfl_xor_sync(0xffffffffu, acc.z, m);
        acc.w += __shfl_xor_sync(0xffffffffu, acc.w, m);
    }
    // every lane now holds the reduced quad for its q.  t_quad = dis*(acc + hd2[node])
    float dis = g_dis[node];
    float4 h = g_h2[node * 4 + q];
    acc.x = dis * (acc.x + h.x);
    acc.y = dis * (acc.y + h.y);
    acc.z = dis * (acc.z + h.z);
    acc.w = dis * (acc.w + h.w);

    // broadcast t[16]: lane j (j<4) holds quad j
    float t[HID];
    #pragma unroll
    for (int j = 0; j < 4; j++) {
        t[4*j+0] = __shfl_sync(0xffffffffu, acc.x, j);
        t[4*j+1] = __shfl_sync(0xffffffffu, acc.y, j);
        t[4*j+2] = __shfl_sync(0xffffffffu, acc.z, j);
        t[4*j+3] = __shfl_sync(0xffffffffu, acc.w, j);
    }

    // outputs split across lanes: o1 = col lane, o2 = col 32+lane (lanes 0..7)
    float o1 = b2s[lane];
    float o2 = (lane < 8) ? b2s[32 + lane] : -1e30f;
    #pragma unroll
    for (int k = 0; k < HID; k++) {
        o1 = fmaf(t[k], w2s[k][lane], o1);
        if (lane < 8) o2 = fmaf(t[k], w2s[k][32 + lane], o2);
    }

    // warp-wide log_softmax over the 40 values
    float m = fmaxf(o1, o2);
    #pragma unroll
    for (int d = 1; d < 32; d <<= 1) m = fmaxf(m, __shfl_xor_sync(0xffffffffu, m, d));
    float s = expf(o1 - m) + ((lane < 8) ? expf(o2 - m) : 0.f);
    #pragma unroll
    for (int d = 1; d < 32; d <<= 1) s += __shfl_xor_sync(0xffffffffu, s, d);
    float lse = m + logf(s);

    float* o = out + (size_t)node * CLS;
    o[lane] = o1 - lse;
    if (lane < 8) o[32 + lane] = o2 - lse;
}

// ---------------------------------------------------------------------------
extern "C" void kernel_launch(void* const* d_in, const int* in_sizes, int n_in,
                              void* d_out, int out_size) {
    const float* x  = (const float*)d_in[0];
    const int*   ei = (const int*)d_in[1];
    const float* ew = (const float*)d_in[2];
    const float* W1 = (const float*)d_in[3];
    const float* b1 = (const float*)d_in[4];
    const float* W2 = (const float*)d_in[5];
    const float* b2 = (const float*)d_in[6];
    float* out = (float*)d_out;

    int N = in_sizes[0] / F_IN;     // 100000
    int E = in_sizes[2];            // 3200000

    const int T = 256;
    init_kernel<<<(N + T - 1) / T, T>>>(N);                      // 0
    cnt_kernel<<<(E + T - 1) / T, T>>>(ei + E, E);               // 1
    scan1_kernel<<<NBLK, SCAN_B>>>(N);                           // 2
    gemm1_kernel<<<(N + GROWS - 1) / GROWS, GT>>>(x, W1, N);     // 3 (profiled)
    scan2_kernel<<<1, 128>>>(N);                                 // 4
    scan3_kernel<<<(N + T - 1) / T, T>>>(N);                     // 5
    fill_kernel<<<(E + T - 1) / T, T>>>(ei, ew, E);              // 6
    degdis_kernel<<<(N * 32 + T - 1) / T, T>>>(N);               // 7
    gather1_kernel<<<(N * 32 + T - 1) / T, T>>>(b1, N);          // 8
    gatherfinal_kernel<<<(N * 32 + T - 1) / T, T>>>(W2, b2, out, N); // 9
}

// round 10
// speedup vs baseline: 1.3421x; 1.3421x over previous
#include <cuda_runtime.h>
#include <math.h>

#define F_IN   512
#define HID    16
#define CLS    40
#define N_MAX  100000
#define E_MAX  3400000
#define SCAN_B 1024
#define NBLK   ((N_MAX + SCAN_B - 1) / SCAN_B)   // 98

// ---------------- scratch (static device globals; no allocation) ------------
__device__ float  g_dis[N_MAX];                 // dis = rsqrt(deg)
__device__ int    g_cnt[N_MAX];                 // in-degree counts
__device__ int    g_off[N_MAX + 1];             // CSR offsets (by col)
__device__ int    g_cursor[N_MAX];              // fill cursors
__device__ int    g_bsum[NBLK];                 // per-block totals
__device__ int    g_boff[NBLK];                 // per-block exclusive offsets
__device__ unsigned long long g_csr[E_MAX];     // packed (w_bits<<32 | row)
__device__ float4 g_h1[N_MAX * 4];              // h1 partials, then dis*h1
__device__ float4 g_h2[N_MAX * 4];              // hd2 = dis*relu(layer1)

// ---------------- helpers ---------------------------------------------------
__device__ __forceinline__ unsigned long long pack2(float lo, float hi) {
    unsigned long long d;
    asm("mov.b64 %0, {%1,%2};" : "=l"(d) : "f"(lo), "f"(hi));
    return d;
}
__device__ __forceinline__ void unpack2(unsigned long long v, float& lo, float& hi) {
    asm("mov.b64 {%0,%1}, %2;" : "=f"(lo), "=f"(hi) : "l"(v));
}
__device__ __forceinline__ unsigned long long fma2(unsigned long long a,
                                                   unsigned long long b,
                                                   unsigned long long c) {
    unsigned long long d;
    asm("fma.rn.f32x2 %0, %1, %2, %3;" : "=l"(d) : "l"(a), "l"(b), "l"(c));
    return d;
}
__device__ __forceinline__ void red_add_v4(float4* addr, float x, float y, float z, float w) {
    asm volatile("red.global.add.v4.f32 [%0], {%1,%2,%3,%4};"
                 :: "l"(addr), "f"(x), "f"(y), "f"(z), "f"(w)
                 : "memory");
}

// ---------------- init: cnt=0, h1=0 (red.add target) ------------------------
__global__ void init_kernel(int N) {
    int i = blockIdx.x * blockDim.x + threadIdx.x;
    if (i < N * 4) g_h1[i] = make_float4(0.f, 0.f, 0.f, 0.f);
    if (i < N) g_cnt[i] = 0;
}

// cnt[col] += 1
__global__ void cnt_kernel(const int* __restrict__ col, int E) {
    int e = blockIdx.x * blockDim.x + threadIdx.x;
    if (e < E) atomicAdd(&g_cnt[col[e]], 1);
}

// ---------------- 3-phase multi-block exclusive scan ------------------------
__global__ __launch_bounds__(SCAN_B) void scan1_kernel(int N) {
    __shared__ int s[SCAN_B];
    int t = threadIdx.x;
    int i = blockIdx.x * SCAN_B + t;
    int v = (i < N) ? g_cnt[i] : 0;
    s[t] = v;
    __syncthreads();
    #pragma unroll
    for (int d = 1; d < SCAN_B; d <<= 1) {
        int u = (t >= d) ? s[t - d] : 0;
        __syncthreads();
        s[t] += u;
        __syncthreads();
    }
    if (i < N) g_off[i] = s[t] - v;                 // exclusive
    if (t == SCAN_B - 1) g_bsum[blockIdx.x] = s[t]; // block total
}

__global__ __launch_bounds__(128) void scan2_kernel(int N) {
    __shared__ int s[128];
    int t = threadIdx.x;
    int v = (t < NBLK) ? g_bsum[t] : 0;
    s[t] = v;
    __syncthreads();
    #pragma unroll
    for (int d = 1; d < 128; d <<= 1) {
        int u = (t >= d) ? s[t - d] : 0;
        __syncthreads();
        s[t] += u;
        __syncthreads();
    }
    if (t < NBLK) g_boff[t] = s[t] - v;
    if (t == 127) g_off[N] = s[t];                  // grand total (= E)
}

__global__ void scan3_kernel(int N) {
    int i = blockIdx.x * blockDim.x + threadIdx.x;
    if (i < N) {
        int o = g_off[i] + g_boff[i / SCAN_B];
        g_off[i] = o;
        g_cursor[i] = o;
    }
}

// fill CSR: append (w, row) to col c
__global__ void fill_kernel(const int* __restrict__ ei, const float* __restrict__ w, int E) {
    int e = blockIdx.x * blockDim.x + threadIdx.x;
    if (e >= E) return;
    int r = ei[e];
    int c = ei[E + e];
    int pos = atomicAdd(&g_cursor[c], 1);
    g_csr[pos] = ((unsigned long long)__float_as_uint(w[e]) << 32) | (unsigned int)r;
}

// ---------------- dense GEMM: h1 += x @ W1  (K-split, f32x2, red.add) -------
#define GT     256                 // threads per block (8 warps)
#define ROWS_B 512                 // rows per block = 256 packed pairs
#define KC     16                  // k-chunk
#define KSPLIT 4
#define KPB    (F_IN / KSPLIT)     // 128 K per block

__global__ __launch_bounds__(GT) void gemm1_kernel(const float* __restrict__ x,
                                                   const float* __restrict__ W1,
                                                   int N) {
    __shared__ float xs[ROWS_B][KC + 1];           // 34.8 KB, bank-conflict-free
    __shared__ unsigned long long ws2[KC][HID];    // W duplicated (w,w)
    int r0 = blockIdx.x * ROWS_B;
    int k0 = blockIdx.y * KPB;

    unsigned long long acc2[HID];
    #pragma unroll
    for (int j = 0; j < HID; j++) acc2[j] = 0ULL;

    for (int kc = k0; kc < k0 + KPB; kc += KC) {
        __syncthreads();
        {   // 256 threads load 256 W elements
            int i = threadIdx.x;
            float wv = W1[(kc + i / HID) * HID + (i % HID)];
            ws2[i / HID][i % HID] = pack2(wv, wv);
        }
        #pragma unroll
        for (int l = 0; l < (ROWS_B * (KC / 4)) / GT; l++) {   // 8 float4 each
            int idx = l * GT + threadIdx.x;
            int rl  = idx / (KC / 4);
            int c4  = idx % (KC / 4);
            int row = r0 + rl;
            float4 v = make_float4(0.f, 0.f, 0.f, 0.f);
            if (row < N)
                v = *(const float4*)(x + (size_t)row * F_IN + kc + c4 * 4);
            xs[rl][c4 * 4 + 0] = v.x;
            xs[rl][c4 * 4 + 1] = v.y;
            xs[rl][c4 * 4 + 2] = v.z;
            xs[rl][c4 * 4 + 3] = v.w;
        }
        __syncthreads();

        #pragma unroll
        for (int kk = 0; kk < KC; kk++) {
            float xa = xs[threadIdx.x][kk];
            float xb = xs[threadIdx.x + 256][kk];
            unsigned long long xp = pack2(xa, xb);
            #pragma unroll
            for (int j = 0; j < HID; j++)
                acc2[j] = fma2(xp, ws2[kk][j], acc2[j]);
        }
    }

    float va[HID], vb[HID];
    #pragma unroll
    for (int j = 0; j < HID; j++) unpack2(acc2[j], va[j], vb[j]);
    int rowA = r0 + threadIdx.x;
    int rowB = r0 + threadIdx.x + 256;
    if (rowA < N) {
        #pragma unroll
        for (int q = 0; q < 4; q++)
            red_add_v4(&g_h1[rowA * 4 + q], va[4*q], va[4*q+1], va[4*q+2], va[4*q+3]);
    }
    if (rowB < N) {
        #pragma unroll
        for (int q = 0; q < 4; q++)
            red_add_v4(&g_h1[rowB * 4 + q], vb[4*q], vb[4*q+1], vb[4*q+2], vb[4*q+3]);
    }
}

// ---------------- deg from CSR; dis = rsqrt; scale h1 *= dis (warp/node) ----
__global__ __launch_bounds__(256) void degdis_kernel(int N) {
    int node = (blockIdx.x * blockDim.x + threadIdx.x) >> 5;
    int lane = threadIdx.x & 31;
    if (node >= N) return;
    int start = g_off[node];
    int end   = g_off[node + 1];
    float s = 0.f;
    for (int e = start + lane; e < end; e += 32)
        s += __uint_as_float((unsigned int)(g_csr[e] >> 32));
    #pragma unroll
    for (int m = 1; m < 32; m <<= 1)
        s += __shfl_xor_sync(0xffffffffu, s, m);
    float dis = rsqrtf(s + 1.0f);        // +1: self-loop weight
    if (lane == 0) g_dis[node] = dis;
    if (lane < 4) {                       // h1 *= dis  (hd = dis*h)
        float4 h = g_h1[node * 4 + lane];
        g_h1[node * 4 + lane] = make_float4(dis * h.x, dis * h.y, dis * h.z, dis * h.w);
    }
}

// ---------------- gather layer 1: hd2 = dis*relu(dis*(Σ w·hd[r] + hd[c])+b1)-
__global__ __launch_bounds__(256) void gather1_kernel(const float* __restrict__ bias, int N) {
    int node = (blockIdx.x * blockDim.x + threadIdx.x) >> 5;
    int lane = threadIdx.x & 31;
    if (node >= N) return;

    int start = g_off[node];
    int end   = g_off[node + 1];
    int sub = lane >> 2;     // 0..7 : edge slot
    int q   = lane & 3;      // 0..3 : float4 quad

    float4 acc = make_float4(0.f, 0.f, 0.f, 0.f);
    for (int e = start + sub; e < end; e += 8) {
        unsigned long long en = g_csr[e];
        int   r = (int)(unsigned int)(en & 0xffffffffULL);
        float w = __uint_as_float((unsigned int)(en >> 32));
        float4 s = g_h1[r * 4 + q];
        acc.x = fmaf(w, s.x, acc.x);
        acc.y = fmaf(w, s.y, acc.y);
        acc.z = fmaf(w, s.z, acc.z);
        acc.w = fmaf(w, s.w, acc.w);
    }
    #pragma unroll
    for (int m = 4; m < 32; m <<= 1) {
        acc.x += __shfl_xor_sync(0xffffffffu, acc.x, m);
        acc.y += __shfl_xor_sync(0xffffffffu, acc.y, m);
        acc.z += __shfl_xor_sync(0xffffffffu, acc.z, m);
        acc.w += __shfl_xor_sync(0xffffffffu, acc.w, m);
    }
    if (lane < 4) {
        float dis = g_dis[node];
        float4 h = g_h1[node * 4 + lane];      // hd[node]: self-loop term
        float4 b = ((const float4*)bias)[lane];
        acc.x = dis * fmaxf(fmaf(dis, acc.x + h.x, b.x), 0.f);
        acc.y = dis * fmaxf(fmaf(dis, acc.y + h.y, b.y), 0.f);
        acc.z = dis * fmaxf(fmaf(dis, acc.z + h.z, b.z), 0.f);
        acc.w = dis * fmaxf(fmaf(dis, acc.w + h.w, b.w), 0.f);
        g_h2[node * 4 + lane] = acc;
    }
}

// ---------------- fused gather layer 2 + W2 GEMM + log_softmax --------------
__global__ __launch_bounds__(256) void gatherfinal_kernel(const float* __restrict__ W2,
                                                          const float* __restrict__ b2,
                                                          float* __restrict__ out,
                                                          int N) {
    __shared__ float w2s[HID][CLS];
    __shared__ float b2s[CLS];
    for (int i = threadIdx.x; i < HID * CLS; i += blockDim.x)
        w2s[i / CLS][i % CLS] = W2[i];
    if (threadIdx.x < CLS) b2s[threadIdx.x] = b2[threadIdx.x];
    __syncthreads();

    int node = (blockIdx.x * blockDim.x + threadIdx.x) >> 5;
    int lane = threadIdx.x & 31;
    if (node >= N) return;

    int start = g_off[node];
    int end   = g_off[node + 1];
    int sub = lane >> 2;
    int q   = lane & 3;

    float4 acc = make_float4(0.f, 0.f, 0.f, 0.f);
    for (int e = start + sub; e < end; e += 8) {
        unsigned long long en = g_csr[e];
        int   r = (int)(unsigned int)(en & 0xffffffffULL);
        float w = __uint_as_float((unsigned int)(en >> 32));
        float4 s = g_h2[r * 4 + q];
        acc.x = fmaf(w, s.x, acc.x);
        acc.y = fmaf(w, s.y, acc.y);
        acc.z = fmaf(w, s.z, acc.z);
        acc.w = fmaf(w, s.w, acc.w);
    }
    #pragma unroll
    for (int m = 4; m < 32; m <<= 1) {
        acc.x += __shfl_xor_sync(0xffffffffu, acc.x, m);
        acc.y += __shfl_xor_sync(0xffffffffu, acc.y, m);
        acc.z += __shfl_xor_sync(0xffffffffu, acc.z, m);
        acc.w += __shfl_xor_sync(0xffffffffu, acc.w, m);
    }
    // t_quad = dis*(acc + hd2[node])  (every lane holds its q's reduced quad)
    float dis = g_dis[node];
    float4 h = g_h2[node * 4 + q];
    acc.x = dis * (acc.x + h.x);
    acc.y = dis * (acc.y + h.y);
    acc.z = dis * (acc.z + h.z);
    acc.w = dis * (acc.w + h.w);

    // broadcast t[16]: lane j (j<4) holds quad j
    float t[HID];
    #pragma unroll
    for (int j = 0; j < 4; j++) {
        t[4*j+0] = __shfl_sync(0xffffffffu, acc.x, j);
        t[4*j+1] = __shfl_sync(0xffffffffu, acc.y, j);
        t[4*j+2] = __shfl_sync(0xffffffffu, acc.z, j);
        t[4*j+3] = __shfl_sync(0xffffffffu, acc.w, j);
    }

    float o1 = b2s[lane];
    float o2 = (lane < 8) ? b2s[32 + lane] : -1e30f;
    #pragma unroll
    for (int k = 0; k < HID; k++) {
        o1 = fmaf(t[k], w2s[k][lane], o1);
        if (lane < 8) o2 = fmaf(t[k], w2s[k][32 + lane], o2);
    }

    float m = fmaxf(o1, o2);
    #pragma unroll
    for (int d = 1; d < 32; d <<= 1) m = fmaxf(m, __shfl_xor_sync(0xffffffffu, m, d));
    float s = expf(o1 - m) + ((lane < 8) ? expf(o2 - m) : 0.f);
    #pragma unroll
    for (int d = 1; d < 32; d <<= 1) s += __shfl_xor_sync(0xffffffffu, s, d);
    float lse = m + logf(s);

    float* o = out + (size_t)node * CLS;
    o[lane] = o1 - lse;
    if (lane < 8) o[32 + lane] = o2 - lse;
}

// ---------------------------------------------------------------------------
extern "C" void kernel_launch(void* const* d_in, const int* in_sizes, int n_in,
                              void* d_out, int out_size) {
    const float* x  = (const float*)d_in[0];
    const int*   ei = (const int*)d_in[1];
    const float* ew = (const float*)d_in[2];
    const float* W1 = (const float*)d_in[3];
    const float* b1 = (const float*)d_in[4];
    const float* W2 = (const float*)d_in[5];
    const float* b2 = (const float*)d_in[6];
    float* out = (float*)d_out;

    int N = in_sizes[0] / F_IN;     // 100000
    int E = in_sizes[2];            // 3200000

    const int T = 256;
    dim3 ggrid((N + ROWS_B - 1) / ROWS_B, KSPLIT);
    init_kernel<<<(N * 4 + T - 1) / T, T>>>(N);                  // 0
    cnt_kernel<<<(E + T - 1) / T, T>>>(ei + E, E);               // 1
    scan1_kernel<<<NBLK, SCAN_B>>>(N);                           // 2
    gemm1_kernel<<<ggrid, GT>>>(x, W1, N);                       // 3 (profiled)
    scan2_kernel<<<1, 128>>>(N);                                 // 4
    scan3_kernel<<<(N + T - 1) / T, T>>>(N);                     // 5
    fill_kernel<<<(E + T - 1) / T, T>>>(ei, ew, E);              // 6
    degdis_kernel<<<(N * 32 + T - 1) / T, T>>>(N);               // 7
    gather1_kernel<<<(N * 32 + T - 1) / T, T>>>(b1, N);          // 8
    gatherfinal_kernel<<<(N * 32 + T - 1) / T, T>>>(W2, b2, out, N); // 9
}